// round 1
// baseline (speedup 1.0000x reference)
#include <cuda_runtime.h>
#include <math.h>

#define EMBED    1024
#define HEADS    16
#define HEAD_DIM 64
#define BATCH    2
#define NSEQ     2048
#define MTOT     (BATCH * NSEQ)      /* 4096 */
#define BH       (BATCH * HEADS)     /* 32   */
#define ATT_SCALE 0.125f             /* 64^-0.5 */

// Scratch (no allocations allowed in kernel_launch)
__device__ float g_q [BH * NSEQ * HEAD_DIM];   // [b*H+h][n][d]
__device__ float g_k [BH * NSEQ * HEAD_DIM];
__device__ float g_v [BH * NSEQ * HEAD_DIM];
__device__ float g_ao[MTOT * EMBED];           // attention output, [b*N+n][h*64+d]

// ---------------------------------------------------------------------------
// Tiled fp32 GEMM: C[m][n] = sum_k A[m][k] * W[n][k] + bias[n]
// BM=BN=128, BK=16, 256 threads, 8x8 microtile per thread.
// MODE 0: A = g_ao (proj), write C row-major to 'C'
// MODE 1: A = param (x), scatter output into g_q/g_k/g_v per QKV layout
// ---------------------------------------------------------------------------
template <int MODE>
__global__ __launch_bounds__(256, 2)
void gemm_kernel(const float* __restrict__ Ain, const float* __restrict__ W,
                 const float* __restrict__ bias, float* __restrict__ C,
                 int M, int Nn, int K)
{
    __shared__ float As[16][128];
    __shared__ float Bs[16][128];

    const float* A = (MODE == 0) ? (const float*)g_ao : Ain;

    const int tid = threadIdx.x;
    const int tx = tid & 15;          // n-group
    const int ty = tid >> 4;          // m-group
    const int m0 = blockIdx.y * 128;
    const int n0 = blockIdx.x * 128;

    float acc[8][8];
#pragma unroll
    for (int i = 0; i < 8; i++)
#pragma unroll
        for (int j = 0; j < 8; j++) acc[i][j] = 0.f;

    for (int k0 = 0; k0 < K; k0 += 16) {
        __syncthreads();
#pragma unroll
        for (int r = 0; r < 2; r++) {
            int p   = tid + r * 256;      // 0..511
            int row = p >> 2;             // 0..127
            int kq  = (p & 3) * 4;        // 0,4,8,12
            float4 va = *(const float4*)&A[(size_t)(m0 + row) * K + k0 + kq];
            As[kq + 0][row] = va.x; As[kq + 1][row] = va.y;
            As[kq + 2][row] = va.z; As[kq + 3][row] = va.w;
            float4 vb = *(const float4*)&W[(size_t)(n0 + row) * K + k0 + kq];
            Bs[kq + 0][row] = vb.x; Bs[kq + 1][row] = vb.y;
            Bs[kq + 2][row] = vb.z; Bs[kq + 3][row] = vb.w;
        }
        __syncthreads();

#pragma unroll
        for (int kk = 0; kk < 16; kk++) {
            float a[8], b[8];
            *(float4*)&a[0] = *(float4*)&As[kk][ty * 8];
            *(float4*)&a[4] = *(float4*)&As[kk][ty * 8 + 4];
            *(float4*)&b[0] = *(float4*)&Bs[kk][tx * 8];
            *(float4*)&b[4] = *(float4*)&Bs[kk][tx * 8 + 4];
#pragma unroll
            for (int i = 0; i < 8; i++)
#pragma unroll
                for (int j = 0; j < 8; j++)
                    acc[i][j] += a[i] * b[j];
        }
    }

    // Epilogue
    if (MODE == 0) {
#pragma unroll
        for (int i = 0; i < 8; i++) {
            int gm = m0 + ty * 8 + i;
#pragma unroll
            for (int jj = 0; jj < 2; jj++) {
                int gn = n0 + tx * 8 + jj * 4;
                float4 r;
                r.x = acc[i][jj * 4 + 0] + bias[gn + 0];
                r.y = acc[i][jj * 4 + 1] + bias[gn + 1];
                r.z = acc[i][jj * 4 + 2] + bias[gn + 2];
                r.w = acc[i][jj * 4 + 3] + bias[gn + 3];
                *(float4*)&C[(size_t)gm * Nn + gn] = r;
            }
        }
    } else {
        // QKV scatter: gn in [0,3072): s=gn/1024 selects q/k/v; within: h=r/64, dh=r%64
#pragma unroll
        for (int i = 0; i < 8; i++) {
            int gm   = m0 + ty * 8 + i;
            int b    = gm >> 11;           // /2048
            int nrow = gm & (NSEQ - 1);
#pragma unroll
            for (int j = 0; j < 8; j++) {
                int gn = n0 + tx * 8 + j;
                int s  = gn >> 10;
                int rr = gn & 1023;
                int h  = rr >> 6;
                int dh = rr & 63;
                float val = acc[i][j] + bias[gn];
                float* dst = (s == 0) ? g_q : (s == 1) ? g_k : g_v;
                dst[(((size_t)(b * HEADS + h)) * NSEQ + nrow) * HEAD_DIM + dh] = val;
            }
        }
    }
}

// ---------------------------------------------------------------------------
// SIMT flash attention (fp32). Grid: (N/128 q-tiles, B*H). 256 threads.
// Q tile 128 rows, K/V tiles 64 rows, online softmax, P staged in smem.
// Dynamic smem: Qt[64][128] + Kt[64][64] + Vs[64][64] + Pt[64][128] = 96KB
// ---------------------------------------------------------------------------
__global__ __launch_bounds__(256, 2)
void flash_kernel()
{
    extern __shared__ float sm[];
    float* Qt = sm;                       // [d][q]  64*128
    float* Kt = Qt + 64 * 128;            // [d][k]  64*64
    float* Vs = Kt + 64 * 64;             // [k][d]  64*64
    float* Pt = Vs + 64 * 64;             // [k][q]  64*128

    const int tid = threadIdx.x;
    const int tx = tid & 15;              // k-group (S) / d-group (O)
    const int ty = tid >> 4;              // q-group
    const int bh = blockIdx.y;
    const int q0 = blockIdx.x * 128;

    const float* qp = g_q + (size_t)bh * NSEQ * HEAD_DIM;
    const float* kp = g_k + (size_t)bh * NSEQ * HEAD_DIM;
    const float* vp = g_v + (size_t)bh * NSEQ * HEAD_DIM;

    // Load Q tile transposed: 128x64 -> Qt[d][q]
#pragma unroll
    for (int r = 0; r < 8; r++) {
        int p   = tid + r * 256;          // 0..2047
        int row = p >> 4;                 // 0..127
        int dq  = (p & 15) * 4;           // 0..60
        float4 v = *(const float4*)&qp[(size_t)(q0 + row) * HEAD_DIM + dq];
        Qt[(dq + 0) * 128 + row] = v.x;
        Qt[(dq + 1) * 128 + row] = v.y;
        Qt[(dq + 2) * 128 + row] = v.z;
        Qt[(dq + 3) * 128 + row] = v.w;
    }

    float m_i[8], l_i[8], o[8][4];
#pragma unroll
    for (int i = 0; i < 8; i++) {
        m_i[i] = -INFINITY;
        l_i[i] = 0.f;
#pragma unroll
        for (int j = 0; j < 4; j++) o[i][j] = 0.f;
    }

    for (int t = 0; t < NSEQ / 64; t++) {
        __syncthreads();   // previous PV done; safe to overwrite Kt/Vs
        int kbase = t * 64;
#pragma unroll
        for (int r = 0; r < 4; r++) {
            int p   = tid + r * 256;      // 0..1023
            int row = p >> 4;             // 0..63
            int dq  = (p & 15) * 4;
            float4 kv = *(const float4*)&kp[(size_t)(kbase + row) * HEAD_DIM + dq];
            Kt[(dq + 0) * 64 + row] = kv.x;
            Kt[(dq + 1) * 64 + row] = kv.y;
            Kt[(dq + 2) * 64 + row] = kv.z;
            Kt[(dq + 3) * 64 + row] = kv.w;
            float4 vv = *(const float4*)&vp[(size_t)(kbase + row) * HEAD_DIM + dq];
            *(float4*)&Vs[row * 64 + dq] = vv;
        }
        __syncthreads();

        // S = Q K^T (tile 128x64), microtile 8x4
        float s[8][4];
#pragma unroll
        for (int i = 0; i < 8; i++)
#pragma unroll
            for (int j = 0; j < 4; j++) s[i][j] = 0.f;

#pragma unroll 8
        for (int d = 0; d < 64; d++) {
            float a[8], b4[4];
            *(float4*)&a[0]  = *(float4*)&Qt[d * 128 + ty * 8];
            *(float4*)&a[4]  = *(float4*)&Qt[d * 128 + ty * 8 + 4];
            *(float4*)&b4[0] = *(float4*)&Kt[d * 64 + tx * 4];
#pragma unroll
            for (int i = 0; i < 8; i++)
#pragma unroll
                for (int j = 0; j < 4; j++)
                    s[i][j] += a[i] * b4[j];
        }

        // Online softmax per q-row (reduce over 16 tx lanes via shuffle)
#pragma unroll
        for (int i = 0; i < 8; i++) {
            float mt = -INFINITY;
#pragma unroll
            for (int j = 0; j < 4; j++) {
                s[i][j] *= ATT_SCALE;
                mt = fmaxf(mt, s[i][j]);
            }
#pragma unroll
            for (int msk = 1; msk < 16; msk <<= 1)
                mt = fmaxf(mt, __shfl_xor_sync(0xffffffffu, mt, msk));
            float mn  = fmaxf(m_i[i], mt);
            float fac = __expf(m_i[i] - mn);
            float ps  = 0.f;
#pragma unroll
            for (int j = 0; j < 4; j++) {
                float pv = __expf(s[i][j] - mn);
                s[i][j] = pv;
                ps += pv;
            }
#pragma unroll
            for (int msk = 1; msk < 16; msk <<= 1)
                ps += __shfl_xor_sync(0xffffffffu, ps, msk);
            l_i[i] = l_i[i] * fac + ps;
            m_i[i] = mn;
#pragma unroll
            for (int j = 0; j < 4; j++) o[i][j] *= fac;
            // stage P transposed for the PV matmul
#pragma unroll
            for (int j = 0; j < 4; j++)
                Pt[(tx * 4 + j) * 128 + ty * 8 + i] = s[i][j];
        }
        __syncthreads();

        // O += P V  (reduction over 64 keys), microtile 8x4
#pragma unroll 8
        for (int k = 0; k < 64; k++) {
            float a[8], b4[4];
            *(float4*)&a[0]  = *(float4*)&Pt[k * 128 + ty * 8];
            *(float4*)&a[4]  = *(float4*)&Pt[k * 128 + ty * 8 + 4];
            *(float4*)&b4[0] = *(float4*)&Vs[k * 64 + tx * 4];
#pragma unroll
            for (int i = 0; i < 8; i++)
#pragma unroll
                for (int j = 0; j < 4; j++)
                    o[i][j] += a[i] * b4[j];
        }
    }

    // Normalize + write to g_ao[b*N+q][h*64 + d]
    const int b = bh / HEADS, h = bh % HEADS;
#pragma unroll
    for (int i = 0; i < 8; i++) {
        int q = q0 + ty * 8 + i;
        float inv = 1.f / l_i[i];
        float4 r;
        r.x = o[i][0] * inv; r.y = o[i][1] * inv;
        r.z = o[i][2] * inv; r.w = o[i][3] * inv;
        *(float4*)&g_ao[((size_t)(b * NSEQ + q)) * EMBED + h * HEAD_DIM + tx * 4] = r;
    }
}

// ---------------------------------------------------------------------------
// Launch: inputs (metadata order): x, w_qkv, b_qkv, w_proj, b_proj
// ---------------------------------------------------------------------------
extern "C" void kernel_launch(void* const* d_in, const int* in_sizes, int n_in,
                              void* d_out, int out_size)
{
    const float* x      = (const float*)d_in[0];
    const float* w_qkv  = (const float*)d_in[1];
    const float* b_qkv  = (const float*)d_in[2];
    const float* w_proj = (const float*)d_in[3];
    const float* b_proj = (const float*)d_in[4];
    float* out = (float*)d_out;

    // QKV GEMM: [4096,1024] x [3072,1024]^T -> scatter into g_q/g_k/g_v
    gemm_kernel<1><<<dim3(3 * EMBED / 128, MTOT / 128), 256>>>(
        x, w_qkv, b_qkv, nullptr, MTOT, 3 * EMBED, EMBED);

    // Flash attention -> g_ao
    static const size_t smem_bytes = (64 * 128 + 64 * 64 + 64 * 64 + 64 * 128) * sizeof(float);
    cudaFuncSetAttribute(flash_kernel, cudaFuncAttributeMaxDynamicSharedMemorySize,
                         (int)smem_bytes);
    flash_kernel<<<dim3(NSEQ / 128, BH), 256, smem_bytes>>>();

    // Output projection: [4096,1024] x [1024,1024]^T + bias -> d_out
    gemm_kernel<0><<<dim3(EMBED / 128, MTOT / 128), 256>>>(
        nullptr, w_proj, b_proj, out, MTOT, EMBED, EMBED);
}

// round 3
// speedup vs baseline: 3.1063x; 3.1063x over previous
#include <cuda_runtime.h>
#include <math.h>

#define EMBED    1024
#define HEADS    16
#define HEAD_DIM 64
#define BATCH    2
#define NSEQ     2048
#define MTOT     (BATCH * NSEQ)      /* 4096 */
#define BH       (BATCH * HEADS)     /* 32   */
#define ATT_SCALE 0.125f             /* 64^-0.5 */

// Scratch (no allocations allowed)
__device__ float g_q [BH * NSEQ * HEAD_DIM];   // [b*H+h][n][d]
__device__ float g_k [BH * NSEQ * HEAD_DIM];
__device__ float g_v [BH * NSEQ * HEAD_DIM];
__device__ float g_ao[MTOT * EMBED];           // attention out, [b*N+n][h*64+d]

// ---------------------------------------------------------------------------
// tf32 helpers
// ---------------------------------------------------------------------------
__device__ __forceinline__ unsigned f2tf(float x) {
    unsigned u;
    asm("cvt.rna.tf32.f32 %0, %1;" : "=r"(u) : "f"(x));
    return u;
}

__device__ __forceinline__ void mma_tf32(float* d, const unsigned* a,
                                         unsigned b0, unsigned b1) {
    asm volatile(
        "mma.sync.aligned.m16n8k8.row.col.f32.tf32.tf32.f32 "
        "{%0,%1,%2,%3}, {%4,%5,%6,%7}, {%8,%9}, {%0,%1,%2,%3};\n"
        : "+f"(d[0]), "+f"(d[1]), "+f"(d[2]), "+f"(d[3])
        : "r"(a[0]), "r"(a[1]), "r"(a[2]), "r"(a[3]), "r"(b0), "r"(b1));
}

// ---------------------------------------------------------------------------
// tf32 tensor-core GEMM: C[m][n] = sum_k A[m][k]*W[n][k] + bias[n]
// BM=BN=128, BK=32. 256 threads = 8 warps (4 m x 2 n), warp tile 32x64.
// MODE 0: A = g_ao, write C row-major.  MODE 1: A = x, scatter to g_q/g_k/g_v.
// ---------------------------------------------------------------------------
template <int MODE>
__global__ __launch_bounds__(256, 2)
void gemm_tc(const float* __restrict__ Ain, const float* __restrict__ W,
             const float* __restrict__ bias, float* __restrict__ C,
             int M, int Nn, int K)
{
    __shared__ unsigned As[128 * 36];
    __shared__ unsigned Bs[128 * 36];

    const float* A = (MODE == 0) ? (const float*)g_ao : Ain;

    const int tid  = threadIdx.x;
    const int lane = tid & 31;
    const int wid  = tid >> 5;
    const int wm   = (wid & 3) * 32;   // warp row offset in tile
    const int wn   = (wid >> 2) * 64;  // warp col offset in tile
    const int m0   = blockIdx.y * 128;
    const int n0   = blockIdx.x * 128;

    float acc[2][8][4];
#pragma unroll
    for (int i = 0; i < 2; i++)
#pragma unroll
        for (int j = 0; j < 8; j++)
#pragma unroll
            for (int v = 0; v < 4; v++) acc[i][j][v] = 0.f;

    for (int k0 = 0; k0 < K; k0 += 32) {
        __syncthreads();
#pragma unroll
        for (int r = 0; r < 4; r++) {
            int linear = tid + r * 256;        // 0..1023
            int row = linear >> 3;             // 0..127
            int col = (linear & 7) * 4;        // 0..28
            float4 va = *(const float4*)&A[(size_t)(m0 + row) * K + k0 + col];
            uint4 ua = { f2tf(va.x), f2tf(va.y), f2tf(va.z), f2tf(va.w) };
            *(uint4*)&As[row * 36 + col] = ua;
            float4 vb = *(const float4*)&W[(size_t)(n0 + row) * K + k0 + col];
            uint4 ub = { f2tf(vb.x), f2tf(vb.y), f2tf(vb.z), f2tf(vb.w) };
            *(uint4*)&Bs[row * 36 + col] = ub;
        }
        __syncthreads();

#pragma unroll
        for (int kk = 0; kk < 4; kk++) {
            int kc = kk * 8 + (lane & 3);
            unsigned a[2][4];
#pragma unroll
            for (int im = 0; im < 2; im++) {
                int r = wm + im * 16 + (lane >> 2);
                a[im][0] = As[r * 36 + kc];
                a[im][1] = As[(r + 8) * 36 + kc];
                a[im][2] = As[r * 36 + kc + 4];
                a[im][3] = As[(r + 8) * 36 + kc + 4];
            }
            unsigned b[8][2];
#pragma unroll
            for (int in_ = 0; in_ < 8; in_++) {
                int n = wn + in_ * 8 + (lane >> 2);
                b[in_][0] = Bs[n * 36 + kc];
                b[in_][1] = Bs[n * 36 + kc + 4];
            }
#pragma unroll
            for (int im = 0; im < 2; im++)
#pragma unroll
                for (int in_ = 0; in_ < 8; in_++)
                    mma_tf32(acc[im][in_], a[im], b[in_][0], b[in_][1]);
        }
    }

    // Epilogue
#pragma unroll
    for (int im = 0; im < 2; im++) {
#pragma unroll
        for (int in_ = 0; in_ < 8; in_++) {
            int row0 = m0 + wm + im * 16 + (lane >> 2);
            int col  = n0 + wn + in_ * 8 + (lane & 3) * 2;
            float v00 = acc[im][in_][0] + bias[col];
            float v01 = acc[im][in_][1] + bias[col + 1];
            float v10 = acc[im][in_][2] + bias[col];
            float v11 = acc[im][in_][3] + bias[col + 1];
            if (MODE == 0) {
                float2 r0 = { v00, v01 };
                float2 r1 = { v10, v11 };
                *(float2*)&C[(size_t)row0 * Nn + col] = r0;
                *(float2*)&C[(size_t)(row0 + 8) * Nn + col] = r1;
            } else {
                int s  = col >> 10;
                int rr = col & 1023;
                int h  = rr >> 6;
                int dh = rr & 63;
                float* dst = (s == 0) ? g_q : (s == 1) ? g_k : g_v;
#pragma unroll
                for (int rrow = 0; rrow < 2; rrow++) {
                    int gm = row0 + rrow * 8;
                    int b  = gm >> 11;
                    int nr = gm & (NSEQ - 1);
                    float2 val = rrow == 0 ? make_float2(v00, v01)
                                           : make_float2(v10, v11);
                    *(float2*)&dst[(((size_t)(b * HEADS + h)) * NSEQ + nr) * HEAD_DIM + dh] = val;
                }
            }
        }
    }
}

// ---------------------------------------------------------------------------
// tf32 tensor-core flash attention.
// Grid: (N/128 q-tiles, B*H). 256 threads = 8 warps; warp w owns q-rows
// [16w, 16w+16) -> all softmax row reductions stay inside a lane quad.
// Key tiles of 64. Smem stride 72 (==8 mod 32) -> conflict-free frag loads.
// ---------------------------------------------------------------------------
__global__ __launch_bounds__(256, 2)
void flash_tc()
{
    extern __shared__ unsigned sm[];
    unsigned* Qs = sm;                 // [128][72]
    unsigned* Ks = Qs + 128 * 72;      // [64][72]   (key-major, dims in cols)
    unsigned* Vs = Ks + 64 * 72;       // [64][72]   (key-major, dims in cols)
    unsigned* Ps = Vs + 64 * 72;       // [128][72]  (q-major, keys in cols)

    const int tid   = threadIdx.x;
    const int lane  = tid & 31;
    const int wid   = tid >> 5;
    const int qbase = wid * 16;
    const int bh    = blockIdx.y;
    const int q0    = blockIdx.x * 128;

    const float* qp = g_q + (size_t)bh * NSEQ * HEAD_DIM;
    const float* kp = g_k + (size_t)bh * NSEQ * HEAD_DIM;
    const float* vp = g_v + (size_t)bh * NSEQ * HEAD_DIM;

    // Load Q tile (128x64), cvt to tf32
#pragma unroll
    for (int r = 0; r < 8; r++) {
        int linear = tid + r * 256;         // 0..2047
        int row = linear >> 4;              // 0..127
        int col = (linear & 15) * 4;        // 0..60
        float4 v = *(const float4*)&qp[(size_t)(q0 + row) * HEAD_DIM + col];
        uint4 u = { f2tf(v.x), f2tf(v.y), f2tf(v.z), f2tf(v.w) };
        *(uint4*)&Qs[row * 72 + col] = u;
    }

    float m_i[2] = { -INFINITY, -INFINITY };
    float l_i[2] = { 0.f, 0.f };
    float o[8][4];
#pragma unroll
    for (int n = 0; n < 8; n++)
#pragma unroll
        for (int v = 0; v < 4; v++) o[n][v] = 0.f;

    const int r_in_q = lane >> 2;   // 0..7
    const int c_in_q = lane & 3;    // 0..3

    for (int t = 0; t < NSEQ / 64; t++) {
        __syncthreads();             // prev PV done -> Ks/Vs reusable
        int kb = t * 64;
#pragma unroll
        for (int r = 0; r < 4; r++) {
            int linear = tid + r * 256;     // 0..1023
            int row = linear >> 4;          // 0..63
            int col = (linear & 15) * 4;
            float4 kv = *(const float4*)&kp[(size_t)(kb + row) * HEAD_DIM + col];
            uint4 uk = { f2tf(kv.x), f2tf(kv.y), f2tf(kv.z), f2tf(kv.w) };
            *(uint4*)&Ks[row * 72 + col] = uk;
            float4 vv = *(const float4*)&vp[(size_t)(kb + row) * HEAD_DIM + col];
            uint4 uv = { f2tf(vv.x), f2tf(vv.y), f2tf(vv.z), f2tf(vv.w) };
            *(uint4*)&Vs[row * 72 + col] = uv;
        }
        __syncthreads();

        // S = Q K^T  (warp tile 16 x 64); k-dim = head dims (64)
        float s_[8][4];
#pragma unroll
        for (int n = 0; n < 8; n++)
#pragma unroll
            for (int v = 0; v < 4; v++) s_[n][v] = 0.f;

#pragma unroll
        for (int kk = 0; kk < 8; kk++) {
            int kc = kk * 8 + c_in_q;       // dim index
            unsigned a[4];
            a[0] = Qs[(qbase + r_in_q) * 72 + kc];
            a[1] = Qs[(qbase + r_in_q + 8) * 72 + kc];
            a[2] = Qs[(qbase + r_in_q) * 72 + kc + 4];
            a[3] = Qs[(qbase + r_in_q + 8) * 72 + kc + 4];
#pragma unroll
            for (int nat = 0; nat < 8; nat++) {
                int key = nat * 8 + r_in_q;
                unsigned b0 = Ks[key * 72 + kc];
                unsigned b1 = Ks[key * 72 + kc + 4];
                mma_tf32(s_[nat], a, b0, b1);
            }
        }

        // Online softmax. Thread's rows: r0 = qbase+r_in_q (vals 0,1), r1 = r0+8 (vals 2,3)
        float mt0 = -INFINITY, mt1 = -INFINITY;
#pragma unroll
        for (int nat = 0; nat < 8; nat++) {
#pragma unroll
            for (int v = 0; v < 4; v++) s_[nat][v] *= ATT_SCALE;
            mt0 = fmaxf(mt0, fmaxf(s_[nat][0], s_[nat][1]));
            mt1 = fmaxf(mt1, fmaxf(s_[nat][2], s_[nat][3]));
        }
#pragma unroll
        for (int msk = 1; msk < 4; msk <<= 1) {
            mt0 = fmaxf(mt0, __shfl_xor_sync(0xffffffffu, mt0, msk));
            mt1 = fmaxf(mt1, __shfl_xor_sync(0xffffffffu, mt1, msk));
        }
        float mn0 = fmaxf(m_i[0], mt0);
        float mn1 = fmaxf(m_i[1], mt1);
        float fac0 = __expf(m_i[0] - mn0);
        float fac1 = __expf(m_i[1] - mn1);
        float rs0 = 0.f, rs1 = 0.f;
#pragma unroll
        for (int nat = 0; nat < 8; nat++) {
            s_[nat][0] = __expf(s_[nat][0] - mn0);
            s_[nat][1] = __expf(s_[nat][1] - mn0);
            s_[nat][2] = __expf(s_[nat][2] - mn1);
            s_[nat][3] = __expf(s_[nat][3] - mn1);
            rs0 += s_[nat][0] + s_[nat][1];
            rs1 += s_[nat][2] + s_[nat][3];
        }
#pragma unroll
        for (int msk = 1; msk < 4; msk <<= 1) {
            rs0 += __shfl_xor_sync(0xffffffffu, rs0, msk);
            rs1 += __shfl_xor_sync(0xffffffffu, rs1, msk);
        }
        l_i[0] = l_i[0] * fac0 + rs0;
        l_i[1] = l_i[1] * fac1 + rs1;
        m_i[0] = mn0;
        m_i[1] = mn1;
#pragma unroll
        for (int nat = 0; nat < 8; nat++) {
            o[nat][0] *= fac0; o[nat][1] *= fac0;
            o[nat][2] *= fac1; o[nat][3] *= fac1;
        }

        // Stage P (tf32) in warp-private smem rows
#pragma unroll
        for (int nat = 0; nat < 8; nat++) {
            int pc = nat * 8 + c_in_q * 2;
            int pr = qbase + r_in_q;
            uint2 u0 = { f2tf(s_[nat][0]), f2tf(s_[nat][1]) };
            uint2 u1 = { f2tf(s_[nat][2]), f2tf(s_[nat][3]) };
            *(uint2*)&Ps[pr * 72 + pc] = u0;
            *(uint2*)&Ps[(pr + 8) * 72 + pc] = u1;
        }
        __syncwarp();

        // O += P V  (k-dim = 64 keys)
#pragma unroll
        for (int kk = 0; kk < 8; kk++) {
            int kc = kk * 8 + c_in_q;       // key index
            int pr = qbase + r_in_q;
            unsigned a[4];
            a[0] = Ps[pr * 72 + kc];
            a[1] = Ps[(pr + 8) * 72 + kc];
            a[2] = Ps[pr * 72 + kc + 4];
            a[3] = Ps[(pr + 8) * 72 + kc + 4];
#pragma unroll
            for (int nat = 0; nat < 8; nat++) {
                int dim = nat * 8 + r_in_q;
                unsigned b0 = Vs[kc * 72 + dim];
                unsigned b1 = Vs[(kc + 4) * 72 + dim];
                mma_tf32(o[nat], a, b0, b1);
            }
        }
        __syncwarp();
    }

    // Normalize + write to g_ao[b*N+q][h*64 + d]
    const int b = bh >> 4, h = bh & 15;
    const float inv0 = 1.f / l_i[0];
    const float inv1 = 1.f / l_i[1];
    const int gq0 = q0 + qbase + r_in_q;
#pragma unroll
    for (int nat = 0; nat < 8; nat++) {
        int col = h * HEAD_DIM + nat * 8 + c_in_q * 2;
        float2 r0 = { o[nat][0] * inv0, o[nat][1] * inv0 };
        float2 r1 = { o[nat][2] * inv1, o[nat][3] * inv1 };
        *(float2*)&g_ao[((size_t)(b * NSEQ + gq0)) * EMBED + col] = r0;
        *(float2*)&g_ao[((size_t)(b * NSEQ + gq0 + 8)) * EMBED + col] = r1;
    }
}

// ---------------------------------------------------------------------------
// Launch: inputs (metadata order): x, w_qkv, b_qkv, w_proj, b_proj
// ---------------------------------------------------------------------------
extern "C" void kernel_launch(void* const* d_in, const int* in_sizes, int n_in,
                              void* d_out, int out_size)
{
    const float* x      = (const float*)d_in[0];
    const float* w_qkv  = (const float*)d_in[1];
    const float* b_qkv  = (const float*)d_in[2];
    const float* w_proj = (const float*)d_in[3];
    const float* b_proj = (const float*)d_in[4];
    float* out = (float*)d_out;

    // QKV GEMM: [4096,1024] x [3072,1024]^T -> scatter into g_q/g_k/g_v
    gemm_tc<1><<<dim3(3 * EMBED / 128, MTOT / 128), 256>>>(
        x, w_qkv, b_qkv, nullptr, MTOT, 3 * EMBED, EMBED);

    // Flash attention (tf32 tensor cores) -> g_ao
    static const size_t smem_bytes = (size_t)(128 + 64 + 64 + 128) * 72 * 4;
    cudaFuncSetAttribute(flash_tc, cudaFuncAttributeMaxDynamicSharedMemorySize,
                         (int)smem_bytes);
    flash_tc<<<dim3(NSEQ / 128, BH), 256, smem_bytes>>>();

    // Output projection: [4096,1024] x [1024,1024]^T + bias -> d_out
    gemm_tc<0><<<dim3(EMBED / 128, MTOT / 128), 256>>>(
        nullptr, w_proj, b_proj, out, MTOT, EMBED, EMBED);
}

// round 9
// speedup vs baseline: 4.3168x; 1.3897x over previous
#include <cuda_runtime.h>
#include <cuda_fp16.h>
#include <math.h>

#define EMBED    1024
#define HEADS    16
#define HEAD_DIM 64
#define BATCH    2
#define NSEQ     2048
#define MTOT     (BATCH * NSEQ)      /* 4096 */
#define BH       (BATCH * HEADS)     /* 32   */

// Scratch (no allocations allowed) — fp16
__device__ __half g_q [BH * NSEQ * HEAD_DIM];   // [b*H+h][n][d]
__device__ __half g_k [BH * NSEQ * HEAD_DIM];
__device__ __half g_v [BH * NSEQ * HEAD_DIM];
__device__ __half g_ao[MTOT * EMBED];           // attention out, [b*N+n][h*64+d]

// ---------------------------------------------------------------------------
// helpers
// ---------------------------------------------------------------------------
__device__ __forceinline__ unsigned pkh2(float a, float b) {
    __half2 h = __floats2half2_rn(a, b);
    return *(unsigned*)&h;
}

__device__ __forceinline__ void mma_f16(float* d, const unsigned* a,
                                        unsigned b0, unsigned b1) {
    asm volatile(
        "mma.sync.aligned.m16n8k16.row.col.f32.f16.f16.f32 "
        "{%0,%1,%2,%3}, {%4,%5,%6,%7}, {%8,%9}, {%0,%1,%2,%3};\n"
        : "+f"(d[0]), "+f"(d[1]), "+f"(d[2]), "+f"(d[3])
        : "r"(a[0]), "r"(a[1]), "r"(a[2]), "r"(a[3]), "r"(b0), "r"(b1));
}

// ---------------------------------------------------------------------------
// fp16 tensor-core GEMM: C[m][n] = sum_k A[m][k]*W[n][k] + bias[n]
// BM=BN=128, BK=32, double-buffered smem with register-held prefetch.
// 256 thr = 8 warps (4m x 2n), warp tile 32x64, mma m16n8k16.
// MODE 1: A = x (fp32), scatter fp16 into g_q/g_k/g_v.
// MODE 0: A = g_ao (fp16), write fp32 C row-major.
// ---------------------------------------------------------------------------
template <int MODE>
__global__ __launch_bounds__(256, 2)
void gemm_tc(const float* __restrict__ Ain, const float* __restrict__ W,
             const float* __restrict__ bias, float* __restrict__ C,
             int M, int Nn, int K)
{
    __shared__ __align__(16) __half As[2][128 * 40];
    __shared__ __align__(16) __half Bs[2][128 * 40];

    const int tid  = threadIdx.x;
    const int lane = tid & 31;
    const int wid  = tid >> 5;
    const int g    = lane >> 2;       // 0..7
    const int c    = lane & 3;        // 0..3
    const int wm   = (wid & 3) * 32;
    const int wn   = (wid >> 2) * 64;
    const int m0   = blockIdx.y * 128;
    const int n0   = blockIdx.x * 128;

    const int srow = tid >> 1;        // 0..127
    const int scol = (tid & 1) * 16;  // 0 or 16

    float acc[2][8][4];
#pragma unroll
    for (int i = 0; i < 2; i++)
#pragma unroll
        for (int j = 0; j < 8; j++)
#pragma unroll
            for (int v = 0; v < 4; v++) acc[i][j][v] = 0.f;

    // staging registers (held across compute for latency overlap)
    float4 ra[4];      // MODE 1 A (fp32)
    uint4  ha[2];      // MODE 0 A (fp16)
    float4 rb[4];      // W (fp32) both modes

    const __half* Ah = (const __half*)g_ao;

    auto G2R = [&](int s) {
        int k0 = s * 32;
        if (MODE == 1) {
#pragma unroll
            for (int i = 0; i < 4; i++)
                ra[i] = *(const float4*)&Ain[(size_t)(m0 + srow) * K + k0 + scol + i * 4];
        } else {
            ha[0] = *(const uint4*)&Ah[(size_t)(m0 + srow) * K + k0 + scol];
            ha[1] = *(const uint4*)&Ah[(size_t)(m0 + srow) * K + k0 + scol + 8];
        }
#pragma unroll
        for (int i = 0; i < 4; i++)
            rb[i] = *(const float4*)&W[(size_t)(n0 + srow) * K + k0 + scol + i * 4];
    };

    auto R2S = [&](int buf) {
        __half* ap = &As[buf][srow * 40 + scol];
        if (MODE == 1) {
            uint4 u0, u1;
            u0.x = pkh2(ra[0].x, ra[0].y); u0.y = pkh2(ra[0].z, ra[0].w);
            u0.z = pkh2(ra[1].x, ra[1].y); u0.w = pkh2(ra[1].z, ra[1].w);
            u1.x = pkh2(ra[2].x, ra[2].y); u1.y = pkh2(ra[2].z, ra[2].w);
            u1.z = pkh2(ra[3].x, ra[3].y); u1.w = pkh2(ra[3].z, ra[3].w);
            *(uint4*)ap = u0; *(uint4*)(ap + 8) = u1;
        } else {
            *(uint4*)ap = ha[0]; *(uint4*)(ap + 8) = ha[1];
        }
        __half* bp = &Bs[buf][srow * 40 + scol];
        uint4 w0, w1;
        w0.x = pkh2(rb[0].x, rb[0].y); w0.y = pkh2(rb[0].z, rb[0].w);
        w0.z = pkh2(rb[1].x, rb[1].y); w0.w = pkh2(rb[1].z, rb[1].w);
        w1.x = pkh2(rb[2].x, rb[2].y); w1.y = pkh2(rb[2].z, rb[2].w);
        w1.z = pkh2(rb[3].x, rb[3].y); w1.w = pkh2(rb[3].z, rb[3].w);
        *(uint4*)bp = w0; *(uint4*)(bp + 8) = w1;
    };

    const int NSTEP = K / 32;
    G2R(0);
    R2S(0);
    __syncthreads();

    for (int s = 0; s < NSTEP; s++) {
        const int buf = s & 1;
        const bool pf = (s + 1 < NSTEP);
        if (pf) G2R(s + 1);     // loads in flight during compute

#pragma unroll
        for (int ks = 0; ks < 2; ks++) {
            const int kc2 = ks * 16 + c * 2;
            unsigned a[2][4];
#pragma unroll
            for (int im = 0; im < 2; im++) {
                const __half* ab = &As[buf][(wm + im * 16 + g) * 40 + kc2];
                a[im][0] = *(const unsigned*)ab;
                a[im][1] = *(const unsigned*)(ab + 8 * 40);
                a[im][2] = *(const unsigned*)(ab + 8);
                a[im][3] = *(const unsigned*)(ab + 8 * 40 + 8);
            }
#pragma unroll
            for (int in_ = 0; in_ < 8; in_++) {
                const __half* bb = &Bs[buf][(wn + in_ * 8 + g) * 40 + kc2];
                unsigned b0 = *(const unsigned*)bb;
                unsigned b1 = *(const unsigned*)(bb + 8);
                mma_f16(acc[0][in_], a[0], b0, b1);
                mma_f16(acc[1][in_], a[1], b0, b1);
            }
        }

        if (pf) R2S(buf ^ 1);
        __syncthreads();
    }

    // Epilogue
#pragma unroll
    for (int im = 0; im < 2; im++) {
#pragma unroll
        for (int in_ = 0; in_ < 8; in_++) {
            int row0 = m0 + wm + im * 16 + g;
            int col  = n0 + wn + in_ * 8 + c * 2;
            float v00 = acc[im][in_][0] + bias[col];
            float v01 = acc[im][in_][1] + bias[col + 1];
            float v10 = acc[im][in_][2] + bias[col];
            float v11 = acc[im][in_][3] + bias[col + 1];
            if (MODE == 0) {
                float2 r0 = { v00, v01 };
                float2 r1 = { v10, v11 };
                *(float2*)&C[(size_t)row0 * Nn + col] = r0;
                *(float2*)&C[(size_t)(row0 + 8) * Nn + col] = r1;
            } else {
                int sidx = col >> 10;
                int rr = col & 1023;
                int h  = rr >> 6;
                int dh = rr & 63;
                __half* dst = (sidx == 0) ? g_q : (sidx == 1) ? g_k : g_v;
#pragma unroll
                for (int rrow = 0; rrow < 2; rrow++) {
                    int gm = row0 + rrow * 8;
                    int b  = gm >> 11;
                    int nr = gm & (NSEQ - 1);
                    __half2 val = rrow == 0 ? __floats2half2_rn(v00, v01)
                                            : __floats2half2_rn(v10, v11);
                    *(__half2*)&dst[(((size_t)(b * HEADS + h)) * NSEQ + nr) * HEAD_DIM + dh] = val;
                }
            }
        }
    }
}

// ---------------------------------------------------------------------------
// fp16 tensor-core flash attention. Grid: (N/128, B*H). 256 thr = 8 warps;
// warp w owns q-rows [16w,16w+16). Scale 0.125 (exact in fp16) folded into Q.
// K tiles of 64 with register prefetch of the next tile. Strides 72 halves.
// ---------------------------------------------------------------------------
__global__ __launch_bounds__(256, 2)
void flash_tc()
{
    extern __shared__ __half sm[];
    __half* Qs = sm;                  // [128][72]
    __half* Ks = Qs + 128 * 72;       // [64][72]  key-major, dims in cols
    __half* Vt = Ks + 64 * 72;        // [64][72]  dim-major, keys in cols
    __half* Ps = Vt + 64 * 72;        // [128][72] q-major, keys in cols

    const int tid   = threadIdx.x;
    const int lane  = tid & 31;
    const int wid   = tid >> 5;
    const int g     = lane >> 2;
    const int c     = lane & 3;
    const int qbase = wid * 16;
    const int bh    = blockIdx.y;
    const int q0    = blockIdx.x * 128;

    const __half* qp = g_q + (size_t)bh * NSEQ * HEAD_DIM;
    const __half* kp = g_k + (size_t)bh * NSEQ * HEAD_DIM;
    const __half* vp = g_v + (size_t)bh * NSEQ * HEAD_DIM;

    // Load Q tile (128x64 halves), fold in softmax scale (2^-3, exact)
    const __half2 sc2 = __floats2half2_rn(0.125f, 0.125f);
#pragma unroll
    for (int r = 0; r < 4; r++) {
        int idx = tid + r * 256;            // 0..1023
        int row = idx >> 3;                 // 0..127
        int col = (idx & 7) * 8;            // 0..56
        uint4 u = *(const uint4*)&qp[(size_t)(q0 + row) * HEAD_DIM + col];
        __half2* hp = (__half2*)&u;
        hp[0] = __hmul2(hp[0], sc2); hp[1] = __hmul2(hp[1], sc2);
        hp[2] = __hmul2(hp[2], sc2); hp[3] = __hmul2(hp[3], sc2);
        *(uint4*)&Qs[row * 72 + col] = u;
    }

    float m_i[2] = { -INFINITY, -INFINITY };
    float l_i[2] = { 0.f, 0.f };
    float o[8][4];
#pragma unroll
    for (int n = 0; n < 8; n++)
#pragma unroll
        for (int v = 0; v < 4; v++) o[n][v] = 0.f;

    uint4 rk[2], rv[2];
    auto loadKV = [&](int t) {
        int kb = t * 64;
#pragma unroll
        for (int r = 0; r < 2; r++) {
            int idx = tid + r * 256;        // 0..511
            int key = idx >> 3;             // 0..63
            int col = (idx & 7) * 8;
            rk[r] = *(const uint4*)&kp[(size_t)(kb + key) * HEAD_DIM + col];
            rv[r] = *(const uint4*)&vp[(size_t)(kb + key) * HEAD_DIM + col];
        }
    };
    auto storeKV = [&]() {
#pragma unroll
        for (int r = 0; r < 2; r++) {
            int idx = tid + r * 256;
            int key = idx >> 3;
            int col = (idx & 7) * 8;
            *(uint4*)&Ks[key * 72 + col] = rk[r];
            const __half* h = (const __half*)&rv[r];
#pragma unroll
            for (int j = 0; j < 8; j++) Vt[(col + j) * 72 + key] = h[j];
        }
    };

    loadKV(0);

    for (int t = 0; t < NSEQ / 64; t++) {
        __syncthreads();                    // prev tile's compute done
        storeKV();
        __syncthreads();
        if (t + 1 < NSEQ / 64) loadKV(t + 1);   // overlap with compute

        // S = Q K^T (warp tile 16x64, k-dim = 64 head dims)
        float s_[8][4];
#pragma unroll
        for (int n = 0; n < 8; n++)
#pragma unroll
            for (int v = 0; v < 4; v++) s_[n][v] = 0.f;

#pragma unroll
        for (int ks = 0; ks < 4; ks++) {
            const int kc2 = ks * 16 + c * 2;
            unsigned a[4];
            const __half* qb = &Qs[(qbase + g) * 72 + kc2];
            a[0] = *(const unsigned*)qb;
            a[1] = *(const unsigned*)(qb + 8 * 72);
            a[2] = *(const unsigned*)(qb + 8);
            a[3] = *(const unsigned*)(qb + 8 * 72 + 8);
#pragma unroll
            for (int nat = 0; nat < 8; nat++) {
                const __half* kb2 = &Ks[(nat * 8 + g) * 72 + kc2];
                mma_f16(s_[nat], a, *(const unsigned*)kb2,
                        *(const unsigned*)(kb2 + 8));
            }
        }

        // Online softmax (scale already folded into Q)
        float mt0 = -INFINITY, mt1 = -INFINITY;
#pragma unroll
        for (int nat = 0; nat < 8; nat++) {
            mt0 = fmaxf(mt0, fmaxf(s_[nat][0], s_[nat][1]));
            mt1 = fmaxf(mt1, fmaxf(s_[nat][2], s_[nat][3]));
        }
#pragma unroll
        for (int msk = 1; msk < 4; msk <<= 1) {
            mt0 = fmaxf(mt0, __shfl_xor_sync(0xffffffffu, mt0, msk));
            mt1 = fmaxf(mt1, __shfl_xor_sync(0xffffffffu, mt1, msk));
        }
        float mn0 = fmaxf(m_i[0], mt0);
        float mn1 = fmaxf(m_i[1], mt1);
        float fac0 = __expf(m_i[0] - mn0);
        float fac1 = __expf(m_i[1] - mn1);
        float rs0 = 0.f, rs1 = 0.f;
#pragma unroll
        for (int nat = 0; nat < 8; nat++) {
            s_[nat][0] = __expf(s_[nat][0] - mn0);
            s_[nat][1] = __expf(s_[nat][1] - mn0);
            s_[nat][2] = __expf(s_[nat][2] - mn1);
            s_[nat][3] = __expf(s_[nat][3] - mn1);
            rs0 += s_[nat][0] + s_[nat][1];
            rs1 += s_[nat][2] + s_[nat][3];
        }
#pragma unroll
        for (int msk = 1; msk < 4; msk <<= 1) {
            rs0 += __shfl_xor_sync(0xffffffffu, rs0, msk);
            rs1 += __shfl_xor_sync(0xffffffffu, rs1, msk);
        }
        l_i[0] = l_i[0] * fac0 + rs0;
        l_i[1] = l_i[1] * fac1 + rs1;
        m_i[0] = mn0;
        m_i[1] = mn1;
#pragma unroll
        for (int nat = 0; nat < 8; nat++) {
            o[nat][0] *= fac0; o[nat][1] *= fac0;
            o[nat][2] *= fac1; o[nat][3] *= fac1;
        }

        // Stage P (fp16) in warp-private smem rows
        {
            const int pr = qbase + g;
#pragma unroll
            for (int nat = 0; nat < 8; nat++) {
                int pc = nat * 8 + c * 2;
                *(unsigned*)&Ps[pr * 72 + pc]       = pkh2(s_[nat][0], s_[nat][1]);
                *(unsigned*)&Ps[(pr + 8) * 72 + pc] = pkh2(s_[nat][2], s_[nat][3]);
            }
        }
        __syncwarp();

        // O += P V (k-dim = 64 keys; B from Vt[dim][key])
#pragma unroll
        for (int ks = 0; ks < 4; ks++) {
            const int kc2 = ks * 16 + c * 2;
            unsigned a[4];
            const __half* pb = &Ps[(qbase + g) * 72 + kc2];
            a[0] = *(const unsigned*)pb;
            a[1] = *(const unsigned*)(pb + 8 * 72);
            a[2] = *(const unsigned*)(pb + 8);
            a[3] = *(const unsigned*)(pb + 8 * 72 + 8);
#pragma unroll
            for (int nat = 0; nat < 8; nat++) {
                const __half* vb = &Vt[(nat * 8 + g) * 72 + kc2];
                mma_f16(o[nat], a, *(const unsigned*)vb,
                        *(const unsigned*)(vb + 8));
            }
        }
        __syncwarp();
    }

    // Normalize + write fp16 to g_ao[b*N+q][h*64 + d]
    const int b = bh >> 4, h = bh & 15;
    const float inv0 = 1.f / l_i[0];
    const float inv1 = 1.f / l_i[1];
    const int gq0 = q0 + qbase + g;
#pragma unroll
    for (int nat = 0; nat < 8; nat++) {
        int col = h * HEAD_DIM + nat * 8 + c * 2;
        *(__half2*)&g_ao[((size_t)(b * NSEQ + gq0)) * EMBED + col] =
            __floats2half2_rn(o[nat][0] * inv0, o[nat][1] * inv0);
        *(__half2*)&g_ao[((size_t)(b * NSEQ + gq0 + 8)) * EMBED + col] =
            __floats2half2_rn(o[nat][2] * inv1, o[nat][3] * inv1);
    }
}

// ---------------------------------------------------------------------------
// Launch: inputs (metadata order): x, w_qkv, b_qkv, w_proj, b_proj
// ---------------------------------------------------------------------------
extern "C" void kernel_launch(void* const* d_in, const int* in_sizes, int n_in,
                              void* d_out, int out_size)
{
    const float* x      = (const float*)d_in[0];
    const float* w_qkv  = (const float*)d_in[1];
    const float* b_qkv  = (const float*)d_in[2];
    const float* w_proj = (const float*)d_in[3];
    const float* b_proj = (const float*)d_in[4];
    float* out = (float*)d_out;

    // QKV GEMM: [4096,1024] x [3072,1024]^T -> fp16 scatter into g_q/g_k/g_v
    gemm_tc<1><<<dim3(3 * EMBED / 128, MTOT / 128), 256>>>(
        x, w_qkv, b_qkv, nullptr, MTOT, 3 * EMBED, EMBED);

    // Flash attention (fp16 tensor cores) -> g_ao (fp16)
    static const size_t smem_bytes = (size_t)(128 + 64 + 64 + 128) * 72 * sizeof(__half);
    cudaFuncSetAttribute(flash_tc, cudaFuncAttributeMaxDynamicSharedMemorySize,
                         (int)smem_bytes);
    flash_tc<<<dim3(NSEQ / 128, BH), 256, smem_bytes>>>();

    // Output projection: g_ao(fp16) x [1024,1024]^T + bias -> d_out (fp32)
    gemm_tc<0><<<dim3(EMBED / 128, MTOT / 128), 256>>>(
        nullptr, w_proj, b_proj, out, MTOT, EMBED, EMBED);
}